// round 12
// baseline (speedup 1.0000x reference)
#include <cuda_runtime.h>
#include <math.h>
#include <stdint.h>

#define BB   1024
#define HH   512
#define GG   1536
#define TENC 168
#define TDEC 24
#define NCH  16
#define NCTA 128
#define NT   512
// persistent-kernel smem layout
#define BSM_BYTES (16 * 12288)               // 196608: [ch][sp][kh][row192][16B]
#define WXS_OFF  BSM_BYTES
#define XS_OFF   (WXS_OFF + 192 * 16 * 4)
#define FBS_OFF  (XS_OFF + 64 * 16 * 4)
#define SMEM_P   (FBS_OFF + 192 * 4 + 128)   // ~213.9 KB

// ---------------- persistent device state ----------------
__device__ float g_h[2][BB * HH];
__device__ __align__(16) signed char g_hq[2][2][BB * HH];   // [buf][hi/lo]
__device__ float g_gibase[BB * GG];
__device__ __align__(16) signed char g_Bq[2][2][GG * HH];   // [enc/dec][hi/lo]
__device__ float g_fB[2][GG];
__device__ float g_bc[2][4 * HH];
__device__ unsigned g_cnt;
__device__ volatile unsigned g_gen;

__device__ __forceinline__ float sigmoidf_(float x) { return 1.0f / (1.0f + expf(-x)); }

__device__ __forceinline__ void ldm4(uint32_t r[4], uint32_t a) {
    asm volatile("ldmatrix.sync.aligned.m8n8.x4.shared.b16 {%0,%1,%2,%3}, [%4];"
                 : "=r"(r[0]), "=r"(r[1]), "=r"(r[2]), "=r"(r[3]) : "r"(a));
}
__device__ __forceinline__ void mmai(int* d, const uint32_t* a, uint32_t b0, uint32_t b1) {
    asm volatile(
        "mma.sync.aligned.m16n8k32.row.col.s32.s8.s8.s32 "
        "{%0,%1,%2,%3},{%4,%5,%6,%7},{%8,%9},{%0,%1,%2,%3};"
        : "+r"(d[0]), "+r"(d[1]), "+r"(d[2]), "+r"(d[3])
        : "r"(a[0]), "r"(a[1]), "r"(a[2]), "r"(a[3]), "r"(b0), "r"(b1));
}
__device__ __forceinline__ void cpa16(uint32_t dst, const void* src) {
    asm volatile("cp.async.cg.shared.global [%0], [%1], 16;" :: "r"(dst), "l"(src));
}
__device__ __forceinline__ uint32_t ldcg32(const signed char* p) {
    uint32_t v; asm volatile("ld.global.cg.b32 %0, [%1];" : "=r"(v) : "l"(p)); return v;
}
__device__ __forceinline__ float ldcgf(const float* p) {
    float v; asm volatile("ld.global.cg.f32 %0, [%1];" : "=f"(v) : "l"(p)); return v;
}

// grid-wide barrier: all 128 CTAs co-resident (1 CTA/SM via smem footprint).
// Release: __threadfence before gen bump. Acquire: __threadfence after spin.
__device__ __forceinline__ void grid_sync_() {
    __syncthreads();
    if (threadIdx.x == 0) {
        __threadfence();
        unsigned gen = g_gen;
        if (atomicAdd(&g_cnt, 1u) == NCTA - 1) {
            g_cnt = 0;
            __threadfence();
            g_gen = gen + 1;
        } else {
            while (g_gen == gen) { __nanosleep(64); }
            __threadfence();   // acquire: order subsequent reads after release
        }
    }
    __syncthreads();
}

// ---------------- prep kernels ----------------
__global__ void prep_Bq_kernel(const float* __restrict__ Whe, const float* __restrict__ Whd) {
    const int gw = blockIdx.x * (blockDim.x >> 5) + (threadIdx.x >> 5);
    if (gw >= 2 * GG) return;
    const int which = gw / GG, G = gw - which * GG;
    const int lane = threadIdx.x & 31;
    const float* __restrict__ W = which ? Whd : Whe;
    const size_t base = (size_t)G * HH;
    float mx = 0.0f;
    for (int k = lane; k < HH; k += 32) mx = fmaxf(mx, fabsf(W[base + k]));
#pragma unroll
    for (int off = 16; off; off >>= 1) mx = fmaxf(mx, __shfl_xor_sync(0xffffffffu, mx, off));
    const float s1 = (mx > 0.0f) ? 127.0f / mx : 1.0f;
    const float inv1 = 1.0f / s1;
    for (int k = lane; k < HH; k += 32) {
        const float w = W[base + k];
        const int hi = __float2int_rn(w * s1);
        const int lo = __float2int_rn((w - (float)hi * inv1) * (s1 * 254.0f));
        g_Bq[which][0][base + k] = (signed char)hi;
        g_Bq[which][1][base + k] = (signed char)lo;
    }
    if (lane == 0) g_fB[which][G] = inv1 * (1.0f / 127.0f);
}
__global__ void prep_bc_kernel(const float* __restrict__ bie, const float* __restrict__ bhe,
                               const float* __restrict__ bid, const float* __restrict__ bhd) {
    for (int c = blockIdx.x * blockDim.x + threadIdx.x; c < HH; c += gridDim.x * blockDim.x) {
        g_bc[0][c]          = bie[c] + bhe[c];
        g_bc[0][HH + c]     = bie[512 + c] + bhe[512 + c];
        g_bc[0][2 * HH + c] = bie[1024 + c];
        g_bc[0][3 * HH + c] = bhe[1024 + c];
        g_bc[1][c]          = bhd[c];
        g_bc[1][HH + c]     = bhd[512 + c];
        g_bc[1][2 * HH + c] = 0.0f;
        g_bc[1][3 * HH + c] = bhd[1024 + c];
    }
}
__global__ void zero_h_kernel(int buf) {
    for (int i = blockIdx.x * blockDim.x + threadIdx.x; i < BB * HH;
         i += gridDim.x * blockDim.x) {
        g_h[buf][i] = 0.0f;
        g_hq[buf][0][i] = 0;
        g_hq[buf][1][i] = 0;
    }
}

// ---------------- persistent RNN kernel ----------------
// 128 CTAs = 16 m-tiles x 8 j-tiles; 512 threads = 4 m-warps x 4 n-warps.
// B (weights) resident in smem for the whole kernel; A (h state) global->regs.
template <int DEC, int E, int T>
__global__ __launch_bounds__(NT) void rnn_persist(
    const float* __restrict__ xall, const float* __restrict__ Wxg,
    const float* __restrict__ Wd, const float* __restrict__ bd,
    float* __restrict__ out) {
    extern __shared__ char dsm[];
    const int tid = threadIdx.x, w = tid >> 5, l = tid & 31;
    const int m0 = blockIdx.x * 64, j0 = blockIdx.y * 64;
    const uint32_t sB = (uint32_t)__cvta_generic_to_shared(dsm);
    float* Wxs = (float*)(dsm + WXS_OFF);
    float* xs  = (float*)(dsm + XS_OFF);
    float* fBs = (float*)(dsm + FBS_OFF);

    // one-time prologue: fBs, Wxs, B->smem
    if (tid < 192) fBs[tid] = g_fB[DEC][(tid >> 6) * HH + j0 + (tid & 63)];
    for (int idx = tid; idx < 192 * E; idx += NT) {
        const int n = idx / E, e = idx - n * E;
        const int G = (n >> 6) * HH + j0 + (n & 63);
        Wxs[idx] = DEC ? Wxg[(size_t)G * 528 + 512 + e] : Wxg[G * 8 + e];
    }
    {
        const signed char* Bh = g_Bq[DEC][0];
        const signed char* Bl = g_Bq[DEC][1];
        for (int i = tid; i < 12288; i += NT) {
            const int ch = i / 768, rem = i - ch * 768;
            const int sp = rem / 384, rem2 = rem - sp * 384;
            const int row = rem2 >> 1, kh = rem2 & 1;
            const int G = (row >> 6) * HH + j0 + (row & 63);
            cpa16(sB + ch * 12288 + sp * 6144 + kh * 3072 + row * 16,
                  (sp ? Bl : Bh) + (size_t)G * HH + ch * 32 + kh * 16);
        }
        asm volatile("cp.async.commit_group;");
        asm volatile("cp.async.wait_group 0;");
    }
    __syncthreads();

    const int mbase = (w >> 2) * 16, nloc = (w & 3) * 16;
    const int brow = (l & 7) + ((l >> 4) & 1) * 8, bhalf = (l >> 3) & 1;
    const int aoff = (mbase + (l >> 2)) * HH + (l & 3) * 4;   // A fragment base (bytes)
    const float* __restrict__ bc = g_bc[DEC];
    const float bd0 = DEC ? bd[0] : 0.0f;
    const int qr = l >> 2, qc = (l & 3) * 2;
    const float INV254 = 1.0f / 254.0f;

    for (int t = 0; t < T; t++) {
        const int pi = DEC ? ((t & 1) ^ 1) : (t & 1);
        const int po = pi ^ 1;
        // per-step input tile (consumed in epilogue; sync below)
        const float* xg = xall + (size_t)t * BB * E;
        for (int idx = tid; idx < 64 * E; idx += NT) xs[idx] = xg[m0 * E + idx];

        const signed char* pAh = g_hq[pi][0] + (size_t)m0 * HH + aoff;
        const signed char* pAl = g_hq[pi][1] + (size_t)m0 * HH + aoff;
        auto loadA = [&](int c, uint32_t* ah, uint32_t* al) {
            const int k0 = c * 32;
            ah[0] = ldcg32(pAh + k0);            ah[1] = ldcg32(pAh + 8 * HH + k0);
            ah[2] = ldcg32(pAh + k0 + 16);       ah[3] = ldcg32(pAh + 8 * HH + k0 + 16);
            al[0] = ldcg32(pAl + k0);            al[1] = ldcg32(pAl + 8 * HH + k0);
            al[2] = ldcg32(pAl + k0 + 16);       al[3] = ldcg32(pAl + 8 * HH + k0 + 16);
        };

        int P1[3][2][4], P2[3][2][4];
#pragma unroll
        for (int g = 0; g < 3; g++)
#pragma unroll
            for (int b = 0; b < 2; b++)
#pragma unroll
                for (int q = 0; q < 4; q++) { P1[g][b][q] = 0; P2[g][b][q] = 0; }

        uint32_t Ah[2][4], Al[2][4];
        loadA(0, Ah[0], Al[0]);
        loadA(1, Ah[1], Al[1]);

#pragma unroll
        for (int ch = 0; ch < NCH; ch++) {
            uint32_t nh[4], nl[4];
            if (ch + 2 < NCH) loadA(ch + 2, nh, nl);
            uint32_t bhi[3][4], blo[3][4];
#pragma unroll
            for (int g = 0; g < 3; g++) {
                const uint32_t rb = sB + ch * 12288 + bhalf * 3072 + (g * 64 + nloc + brow) * 16;
                ldm4(bhi[g], rb);
                ldm4(blo[g], rb + 6144);
            }
#pragma unroll
            for (int g = 0; g < 3; g++)
#pragma unroll
                for (int nj = 0; nj < 2; nj++) {
                    mmai(P1[g][nj], Ah[ch & 1], bhi[g][nj * 2], bhi[g][nj * 2 + 1]);
                    mmai(P2[g][nj], Ah[ch & 1], blo[g][nj * 2], blo[g][nj * 2 + 1]);
                    mmai(P2[g][nj], Al[ch & 1], bhi[g][nj * 2], bhi[g][nj * 2 + 1]);
                }
            if (ch + 2 < NCH) {
#pragma unroll
                for (int q = 0; q < 4; q++) { Ah[ch & 1][q] = nh[q]; Al[ch & 1][q] = nl[q]; }
            }
        }
        __syncthreads();   // xs visible for epilogue

        // ---- fused GRU epilogue (bit-identical arithmetic to round 10) ----
        float* __restrict__ h_out = g_h[po];
        signed char* __restrict__ hq_hi = g_hq[po][0];
        signed char* __restrict__ hq_lo = g_hq[po][1];
        const float* __restrict__ hprev = g_h[pi];
#pragma unroll
        for (int nj = 0; nj < 2; nj++) {
            const int cl0 = nloc + nj * 8 + qc;
            const int cb = j0 + cl0;
#pragma unroll
            for (int hf = 0; hf < 2; hf++) {
                const int ml = mbase + qr + hf * 8;
                const int m = m0 + ml;
                const float2 hp = *(const float2*)&hprev[(size_t)m * HH + cb];
                float2 gr = {0.f, 0.f}, gz = {0.f, 0.f}, gn = {0.f, 0.f};
                if (DEC) {
                    gr = *(const float2*)&g_gibase[(size_t)m * GG + cb];
                    gz = *(const float2*)&g_gibase[(size_t)m * GG + HH + cb];
                    gn = *(const float2*)&g_gibase[(size_t)m * GG + 2 * HH + cb];
                }
                float hv[2]; int hqi[2], hql[2];
#pragma unroll
                for (int cc = 0; cc < 2; cc++) {
                    const int q = hf * 2 + cc, cl = cl0 + cc, c = cb + cc;
                    const float pr = ((float)P1[0][nj][q] + (float)P2[0][nj][q] * INV254) * fBs[cl];
                    const float pz = ((float)P1[1][nj][q] + (float)P2[1][nj][q] * INV254) * fBs[64 + cl];
                    const float pn = ((float)P1[2][nj][q] + (float)P2[2][nj][q] * INV254) * fBs[128 + cl];
                    float xr = 0.f, xz = 0.f, xn = 0.f;
#pragma unroll
                    for (int e = 0; e < E; e++) {
                        const float xv = xs[ml * E + e];
                        xr += xv * Wxs[cl * E + e];
                        xz += xv * Wxs[(64 + cl) * E + e];
                        xn += xv * Wxs[(128 + cl) * E + e];
                    }
                    const float ir = (DEC ? (cc ? gr.y : gr.x) : 0.f) + xr;
                    const float iz = (DEC ? (cc ? gz.y : gz.x) : 0.f) + xz;
                    const float in0 = (DEC ? (cc ? gn.y : gn.x) : 0.f) + xn;
                    const float rr = sigmoidf_(pr + ir + bc[c]);
                    const float zz = sigmoidf_(pz + iz + bc[HH + c]);
                    const float nn = tanhf(in0 + bc[2 * HH + c] + rr * (pn + bc[3 * HH + c]));
                    const float h = (1.0f - zz) * nn + zz * (cc ? hp.y : hp.x);
                    hv[cc] = h;
                    const int hi = __float2int_rn(h * 127.0f);
                    hqi[cc] = hi;
                    hql[cc] = __float2int_rn((h - (float)hi * (1.0f / 127.0f)) * 32258.0f);
                }
                float2 ho; ho.x = hv[0]; ho.y = hv[1];
                *(float2*)&h_out[(size_t)m * HH + cb] = ho;
                *(char2*)&hq_hi[(size_t)m * HH + cb] = make_char2((char)hqi[0], (char)hqi[1]);
                *(char2*)&hq_lo[(size_t)m * HH + cb] = make_char2((char)hql[0], (char)hql[1]);
            }
        }

        grid_sync_();   // h^t complete everywhere

        if (DEC && blockIdx.y == 0) {   // fused dense head for step t
            const float* __restrict__ hb = g_h[po];
#pragma unroll
            for (int r = 0; r < 4; r++) {
                const int row = m0 + (w << 2) + r;
                float s = 0.0f;
                for (int k = l; k < HH; k += 32)
                    s += ldcgf(hb + (size_t)row * HH + k) * Wd[k];
#pragma unroll
                for (int off = 16; off; off >>= 1) s += __shfl_down_sync(0xffffffffu, s, off);
                if (l == 0) out[row * TDEC + t] = s + bd0;
            }
        }
    }
}

// ---------------- fp32 base GEMM (once, between phases) ----------------
__global__ __launch_bounds__(256) void base_kernel(const float* __restrict__ W,
                                                   const float* __restrict__ b_ih) {
    __shared__ float As_[16][68];
    __shared__ float Ws_[16][196];
    __shared__ float bihs[192];
    const float* __restrict__ h_in = g_h[0];
    const int tid = threadIdx.x;
    const int tx = tid & 15, ty = tid >> 4;
    const int m0 = blockIdx.x * 64, j0 = blockIdx.y * 64;
    if (tid < 192) bihs[tid] = b_ih[(tid >> 6) * HH + j0 + (tid & 63)];

    float acc[4][12];
#pragma unroll
    for (int i = 0; i < 4; i++)
#pragma unroll
        for (int j = 0; j < 12; j++) acc[i][j] = 0.0f;
    const int r = tid >> 2, kq = (tid & 3) << 2;
    for (int k0 = 0; k0 < HH; k0 += 16) {
        const float4 av  = *(const float4*)(h_in + (size_t)(m0 + r) * HH + k0 + kq);
        const float4 wv0 = *(const float4*)(W + (size_t)(j0 + r) * 528 + k0 + kq);
        const float4 wv1 = *(const float4*)(W + (size_t)(HH + j0 + r) * 528 + k0 + kq);
        const float4 wv2 = *(const float4*)(W + (size_t)(2 * HH + j0 + r) * 528 + k0 + kq);
        __syncthreads();
        As_[kq + 0][r] = av.x; As_[kq + 1][r] = av.y; As_[kq + 2][r] = av.z; As_[kq + 3][r] = av.w;
        Ws_[kq + 0][r] = wv0.x; Ws_[kq + 1][r] = wv0.y; Ws_[kq + 2][r] = wv0.z; Ws_[kq + 3][r] = wv0.w;
        Ws_[kq + 0][64 + r] = wv1.x; Ws_[kq + 1][64 + r] = wv1.y; Ws_[kq + 2][64 + r] = wv1.z; Ws_[kq + 3][64 + r] = wv1.w;
        Ws_[kq + 0][128 + r] = wv2.x; Ws_[kq + 1][128 + r] = wv2.y; Ws_[kq + 2][128 + r] = wv2.z; Ws_[kq + 3][128 + r] = wv2.w;
        __syncthreads();
#pragma unroll
        for (int kk = 0; kk < 16; kk++) {
            const float4 a = *(const float4*)&As_[kk][ty << 2];
            const float4 b0 = *(const float4*)&Ws_[kk][tx << 2];
            const float4 b1 = *(const float4*)&Ws_[kk][64 + (tx << 2)];
            const float4 b2 = *(const float4*)&Ws_[kk][128 + (tx << 2)];
            const float am[4] = {a.x, a.y, a.z, a.w};
            const float bn[12] = {b0.x, b0.y, b0.z, b0.w, b1.x, b1.y, b1.z, b1.w,
                                  b2.x, b2.y, b2.z, b2.w};
#pragma unroll
            for (int i = 0; i < 4; i++)
#pragma unroll
                for (int j = 0; j < 12; j++) acc[i][j] += am[i] * bn[j];
        }
    }
    const int c = tx << 2;
#pragma unroll
    for (int i = 0; i < 4; i++) {
        const int row = m0 + (ty << 2) + i;
#pragma unroll
        for (int g = 0; g < 3; g++) {
            float4 o;
            o.x = acc[i][g * 4 + 0] + bihs[g * 64 + c + 0];
            o.y = acc[i][g * 4 + 1] + bihs[g * 64 + c + 1];
            o.z = acc[i][g * 4 + 2] + bihs[g * 64 + c + 2];
            o.w = acc[i][g * 4 + 3] + bihs[g * 64 + c + 3];
            *(float4*)&g_gibase[(size_t)row * GG + g * HH + j0 + c] = o;
        }
    }
}

extern "C" void kernel_launch(void* const* d_in, const int* in_sizes, int n_in,
                              void* d_out, int out_size) {
    const float* lag      = (const float*)d_in[0];
    const float* curr     = (const float*)d_in[1];
    const float* W_ih_enc = (const float*)d_in[2];
    const float* W_hh_enc = (const float*)d_in[3];
    const float* b_ih_enc = (const float*)d_in[4];
    const float* b_hh_enc = (const float*)d_in[5];
    const float* W_ih_dec = (const float*)d_in[6];
    const float* W_hh_dec = (const float*)d_in[7];
    const float* b_ih_dec = (const float*)d_in[8];
    const float* b_hh_dec = (const float*)d_in[9];
    const float* W_dense  = (const float*)d_in[10];
    const float* b_dense  = (const float*)d_in[11];
    float* out = (float*)d_out;

    cudaFuncSetAttribute(rnn_persist<0, 8, TENC>,
                         cudaFuncAttributeMaxDynamicSharedMemorySize, SMEM_P);
    cudaFuncSetAttribute(rnn_persist<1, 16, TDEC>,
                         cudaFuncAttributeMaxDynamicSharedMemorySize, SMEM_P);

    prep_Bq_kernel<<<384, 256>>>(W_hh_enc, W_hh_dec);
    prep_bc_kernel<<<2, 256>>>(b_ih_enc, b_hh_enc, b_ih_dec, b_hh_dec);
    zero_h_kernel<<<256, 256>>>(0);

    const dim3 grid(16, 8);
    rnn_persist<0, 8, TENC><<<grid, NT, SMEM_P>>>(lag, W_ih_enc,
                                                  (const float*)0, (const float*)0,
                                                  (float*)0);
    // 168 even -> h_T in g_h[0]
    base_kernel<<<grid, 256>>>(W_ih_dec, b_ih_dec);
    zero_h_kernel<<<256, 256>>>(1);
    rnn_persist<1, 16, TDEC><<<grid, NT, SMEM_P>>>(curr, W_ih_dec,
                                                   W_dense, b_dense, out);
}

// round 13
// speedup vs baseline: 1.5193x; 1.5193x over previous
#include <cuda_runtime.h>
#include <math.h>
#include <stdint.h>

#define BB   1024
#define HH   512
#define GG   1536
#define TENC 168
#define TDEC 24
#define NCH  16
#define NCTA 128
#define NT   512
// persistent-kernel smem layout: B resident + Wxs + fBs
#define BSM_BYTES (16 * 12288)               // 196608
#define WXS_OFF  BSM_BYTES
#define FBS_OFF  (WXS_OFF + 192 * 16 * 4)
#define SMEM_P   (FBS_OFF + 192 * 4 + 128)   // ~205.6 KB

// ---------------- persistent device state ----------------
__device__ float g_h[2][BB * HH];
// int8 state in mma-A-FRAGMENT layout: [(m/16)][chunk][lane] -> 16B = {a0,a1,a2,a3}
__device__ __align__(16) signed char g_hqf[2][2][BB * HH];   // [buf][hi/lo]
__device__ float g_gibase[BB * GG];
__device__ __align__(16) signed char g_Bq[2][2][GG * HH];    // [enc/dec][hi/lo]
__device__ float g_fB[2][GG];
__device__ float g_bc[2][4 * HH];
__device__ unsigned g_cnt;
__device__ volatile unsigned g_gen;

__device__ __forceinline__ float sigmoidf_(float x) { return 1.0f / (1.0f + expf(-x)); }

__device__ __forceinline__ void ldm4(uint32_t r[4], uint32_t a) {
    asm volatile("ldmatrix.sync.aligned.m8n8.x4.shared.b16 {%0,%1,%2,%3}, [%4];"
                 : "=r"(r[0]), "=r"(r[1]), "=r"(r[2]), "=r"(r[3]) : "r"(a));
}
__device__ __forceinline__ void mmai(int* d, const uint32_t* a, uint32_t b0, uint32_t b1) {
    asm volatile(
        "mma.sync.aligned.m16n8k32.row.col.s32.s8.s8.s32 "
        "{%0,%1,%2,%3},{%4,%5,%6,%7},{%8,%9},{%0,%1,%2,%3};"
        : "+r"(d[0]), "+r"(d[1]), "+r"(d[2]), "+r"(d[3])
        : "r"(a[0]), "r"(a[1]), "r"(a[2]), "r"(a[3]), "r"(b0), "r"(b1));
}
__device__ __forceinline__ void cpa16(uint32_t dst, const void* src) {
    asm volatile("cp.async.cg.shared.global [%0], [%1], 16;" :: "r"(dst), "l"(src));
}
__device__ __forceinline__ uint4 ldcg128(const signed char* p) {
    uint4 v;
    asm volatile("ld.global.cg.v4.b32 {%0,%1,%2,%3}, [%4];"
                 : "=r"(v.x), "=r"(v.y), "=r"(v.z), "=r"(v.w) : "l"(p));
    return v;
}
__device__ __forceinline__ float ldcgf(const float* p) {
    float v; asm volatile("ld.global.cg.f32 %0, [%1];" : "=f"(v) : "l"(p)); return v;
}

// grid-wide barrier: all 128 CTAs co-resident (1 CTA/SM via smem footprint)
__device__ __forceinline__ void grid_sync_() {
    __syncthreads();
    if (threadIdx.x == 0) {
        __threadfence();
        unsigned gen = g_gen;
        if (atomicAdd(&g_cnt, 1u) == NCTA - 1) {
            g_cnt = 0;
            __threadfence();
            g_gen = gen + 1;
        } else {
            while (g_gen == gen) { __nanosleep(64); }
            __threadfence();
        }
    }
    __syncthreads();
}

// ---------------- prep kernels ----------------
__global__ void prep_Bq_kernel(const float* __restrict__ Whe, const float* __restrict__ Whd) {
    const int gw = blockIdx.x * (blockDim.x >> 5) + (threadIdx.x >> 5);
    if (gw >= 2 * GG) return;
    const int which = gw / GG, G = gw - which * GG;
    const int lane = threadIdx.x & 31;
    const float* __restrict__ W = which ? Whd : Whe;
    const size_t base = (size_t)G * HH;
    float mx = 0.0f;
    for (int k = lane; k < HH; k += 32) mx = fmaxf(mx, fabsf(W[base + k]));
#pragma unroll
    for (int off = 16; off; off >>= 1) mx = fmaxf(mx, __shfl_xor_sync(0xffffffffu, mx, off));
    const float s1 = (mx > 0.0f) ? 127.0f / mx : 1.0f;
    const float inv1 = 1.0f / s1;
    for (int k = lane; k < HH; k += 32) {
        const float w = W[base + k];
        const int hi = __float2int_rn(w * s1);
        const int lo = __float2int_rn((w - (float)hi * inv1) * (s1 * 254.0f));
        g_Bq[which][0][base + k] = (signed char)hi;
        g_Bq[which][1][base + k] = (signed char)lo;
    }
    if (lane == 0) g_fB[which][G] = inv1 * (1.0f / 127.0f);
}
__global__ void prep_bc_kernel(const float* __restrict__ bie, const float* __restrict__ bhe,
                               const float* __restrict__ bid, const float* __restrict__ bhd) {
    for (int c = blockIdx.x * blockDim.x + threadIdx.x; c < HH; c += gridDim.x * blockDim.x) {
        g_bc[0][c]          = bie[c] + bhe[c];
        g_bc[0][HH + c]     = bie[512 + c] + bhe[512 + c];
        g_bc[0][2 * HH + c] = bie[1024 + c];
        g_bc[0][3 * HH + c] = bhe[1024 + c];
        g_bc[1][c]          = bhd[c];
        g_bc[1][HH + c]     = bhd[512 + c];
        g_bc[1][2 * HH + c] = 0.0f;
        g_bc[1][3 * HH + c] = bhd[1024 + c];
    }
}
__global__ void zero_h_kernel(int buf) {
    for (int i = blockIdx.x * blockDim.x + threadIdx.x; i < BB * HH;
         i += gridDim.x * blockDim.x) {
        g_h[buf][i] = 0.0f;
        g_hqf[buf][0][i] = 0;
        g_hqf[buf][1][i] = 0;
    }
}

// ---------------- persistent RNN kernel ----------------
// 128 CTAs = 16 m-tiles x 8 j-tiles; 512 threads = 4 m-warps x 4 n-warps.
// B resident in smem; A (int8 state) in fragment layout: 1 ldcg.128/split/chunk.
template <int DEC, int E, int T>
__global__ __launch_bounds__(NT) void rnn_persist(
    const float* __restrict__ xall, const float* __restrict__ Wxg,
    const float* __restrict__ Wd, const float* __restrict__ bd,
    float* __restrict__ out) {
    extern __shared__ char dsm[];
    const int tid = threadIdx.x, w = tid >> 5, l = tid & 31;
    const int m0 = blockIdx.x * 64, j0 = blockIdx.y * 64;
    const uint32_t sB = (uint32_t)__cvta_generic_to_shared(dsm);
    float* Wxs = (float*)(dsm + WXS_OFF);
    float* fBs = (float*)(dsm + FBS_OFF);

    // one-time prologue: fBs, Wxs, B->smem
    if (tid < 192) fBs[tid] = g_fB[DEC][(tid >> 6) * HH + j0 + (tid & 63)];
    for (int idx = tid; idx < 192 * E; idx += NT) {
        const int n = idx / E, e = idx - n * E;
        const int G = (n >> 6) * HH + j0 + (n & 63);
        Wxs[idx] = DEC ? Wxg[(size_t)G * 528 + 512 + e] : Wxg[G * 8 + e];
    }
    {
        const signed char* Bh = g_Bq[DEC][0];
        const signed char* Bl = g_Bq[DEC][1];
        for (int i = tid; i < 12288; i += NT) {
            const int ch = i / 768, rem = i - ch * 768;
            const int sp = rem / 384, rem2 = rem - sp * 384;
            const int row = rem2 >> 1, kh = rem2 & 1;
            const int G = (row >> 6) * HH + j0 + (row & 63);
            cpa16(sB + ch * 12288 + sp * 6144 + kh * 3072 + row * 16,
                  (sp ? Bl : Bh) + (size_t)G * HH + ch * 32 + kh * 16);
        }
        asm volatile("cp.async.commit_group;");
        asm volatile("cp.async.wait_group 0;");
    }
    __syncthreads();

    const int mbase = (w >> 2) * 16, nloc = (w & 3) * 16;
    const int brow = (l & 7) + ((l >> 4) & 1) * 8, bhalf = (l >> 3) & 1;
    const int ablk = (m0 + mbase) >> 4;      // m-16-block index
    const float* __restrict__ bc = g_bc[DEC];
    const float bd0 = DEC ? bd[0] : 0.0f;
    const int qr = l >> 2, qc = (l & 3) * 2;
    const float INV254 = 1.0f / 254.0f;

    for (int t = 0; t < T; t++) {
        const int pi = DEC ? ((t & 1) ^ 1) : (t & 1);
        const int po = pi ^ 1;

        const signed char* pAh = g_hqf[pi][0] + (size_t)ablk * 8192 + l * 16;
        const signed char* pAl = g_hqf[pi][1] + (size_t)ablk * 8192 + l * 16;

        int P1[3][2][4], P2[3][2][4];
#pragma unroll
        for (int g = 0; g < 3; g++)
#pragma unroll
            for (int b = 0; b < 2; b++)
#pragma unroll
                for (int q = 0; q < 4; q++) { P1[g][b][q] = 0; P2[g][b][q] = 0; }

        uint4 Ah[2], Al[2];
        Ah[0] = ldcg128(pAh);        Al[0] = ldcg128(pAl);
        Ah[1] = ldcg128(pAh + 512);  Al[1] = ldcg128(pAl + 512);

#pragma unroll
        for (int ch = 0; ch < NCH; ch++) {
            uint4 nh, nl;
            if (ch + 2 < NCH) { nh = ldcg128(pAh + (ch + 2) * 512);
                                nl = ldcg128(pAl + (ch + 2) * 512); }
            uint32_t bhi[3][4], blo[3][4];
#pragma unroll
            for (int g = 0; g < 3; g++) {
                const uint32_t rb = sB + ch * 12288 + bhalf * 3072 + (g * 64 + nloc + brow) * 16;
                ldm4(bhi[g], rb);
                ldm4(blo[g], rb + 6144);
            }
            const uint32_t* ah = (const uint32_t*)&Ah[ch & 1];
            const uint32_t* al = (const uint32_t*)&Al[ch & 1];
#pragma unroll
            for (int g = 0; g < 3; g++)
#pragma unroll
                for (int nj = 0; nj < 2; nj++) {
                    mmai(P1[g][nj], ah, bhi[g][nj * 2], bhi[g][nj * 2 + 1]);
                    mmai(P2[g][nj], ah, blo[g][nj * 2], blo[g][nj * 2 + 1]);
                    mmai(P2[g][nj], al, bhi[g][nj * 2], bhi[g][nj * 2 + 1]);
                }
            if (ch + 2 < NCH) { Ah[ch & 1] = nh; Al[ch & 1] = nl; }
        }

        // ---- fused GRU epilogue ----
        float* __restrict__ h_out = g_h[po];
        signed char* __restrict__ hf_hi = g_hqf[po][0];
        signed char* __restrict__ hf_lo = g_hqf[po][1];
        const float* __restrict__ hprev = g_h[pi];
        const float* __restrict__ xg = xall + (size_t)t * BB * E;

#pragma unroll
        for (int hf = 0; hf < 2; hf++) {
            const int row16 = qr + hf * 8;
            const int m = m0 + mbase + row16;
            float xv[E];
#pragma unroll
            for (int e = 0; e < E; e++) xv[e] = __ldg(xg + m * E + e);
#pragma unroll
            for (int nj = 0; nj < 2; nj++) {
                const int cl0 = nloc + nj * 8 + qc;
                const int cb = j0 + cl0;
                const float2 hp = *(const float2*)&hprev[(size_t)m * HH + cb];
                float2 gr = {0.f, 0.f}, gz = {0.f, 0.f}, gn = {0.f, 0.f};
                if (DEC) {
                    gr = *(const float2*)&g_gibase[(size_t)m * GG + cb];
                    gz = *(const float2*)&g_gibase[(size_t)m * GG + HH + cb];
                    gn = *(const float2*)&g_gibase[(size_t)m * GG + 2 * HH + cb];
                }
                float hv[2]; int hqi[2], hql[2];
#pragma unroll
                for (int cc = 0; cc < 2; cc++) {
                    const int q = hf * 2 + cc, cl = cl0 + cc, c = cb + cc;
                    const float pr = ((float)P1[0][nj][q] + (float)P2[0][nj][q] * INV254) * fBs[cl];
                    const float pz = ((float)P1[1][nj][q] + (float)P2[1][nj][q] * INV254) * fBs[64 + cl];
                    const float pn = ((float)P1[2][nj][q] + (float)P2[2][nj][q] * INV254) * fBs[128 + cl];
                    float xr = 0.f, xz = 0.f, xn = 0.f;
#pragma unroll
                    for (int e = 0; e < E; e++) {
                        xr += xv[e] * Wxs[cl * E + e];
                        xz += xv[e] * Wxs[(64 + cl) * E + e];
                        xn += xv[e] * Wxs[(128 + cl) * E + e];
                    }
                    const float ir = (DEC ? (cc ? gr.y : gr.x) : 0.f) + xr;
                    const float iz = (DEC ? (cc ? gz.y : gz.x) : 0.f) + xz;
                    const float in0 = (DEC ? (cc ? gn.y : gn.x) : 0.f) + xn;
                    const float rr = sigmoidf_(pr + ir + bc[c]);
                    const float zz = sigmoidf_(pz + iz + bc[HH + c]);
                    const float nn = tanhf(in0 + bc[2 * HH + c] + rr * (pn + bc[3 * HH + c]));
                    const float h = (1.0f - zz) * nn + zz * (cc ? hp.y : hp.x);
                    hv[cc] = h;
                    const int hi = __float2int_rn(h * 127.0f);
                    hqi[cc] = hi;
                    hql[cc] = __float2int_rn((h - (float)hi * (1.0f / 127.0f)) * 32258.0f);
                }
                float2 ho; ho.x = hv[0]; ho.y = hv[1];
                *(float2*)&h_out[(size_t)m * HH + cb] = ho;
                // fragment-layout int8 store (inverse of loadA mapping)
                const int chunk = cb >> 5;
                const int kin = cb & 31;
                const int kh = kin >> 4, kq = kin & 15;
                const int lp = ((row16 & 7) << 2) + (kq >> 2);
                const int rg = kh * 2 + (row16 >> 3);
                const size_t fa = (size_t)ablk * 8192 + chunk * 512 + lp * 16 + rg * 4 + (kq & 3);
                *(char2*)(hf_hi + fa) = make_char2((char)hqi[0], (char)hqi[1]);
                *(char2*)(hf_lo + fa) = make_char2((char)hql[0], (char)hql[1]);
            }
        }

        grid_sync_();   // h^t complete everywhere

        if (DEC && blockIdx.y == 0) {   // fused dense head for step t
            const float* __restrict__ hb = g_h[po];
#pragma unroll
            for (int r = 0; r < 4; r++) {
                const int row = m0 + (w << 2) + r;
                float s = 0.0f;
                for (int k = l; k < HH; k += 32)
                    s += ldcgf(hb + (size_t)row * HH + k) * Wd[k];
#pragma unroll
                for (int off = 16; off; off >>= 1) s += __shfl_down_sync(0xffffffffu, s, off);
                if (l == 0) out[row * TDEC + t] = s + bd0;
            }
        }
    }
}

// ---------------- fp32 base GEMM (once, between phases) ----------------
__global__ __launch_bounds__(256) void base_kernel(const float* __restrict__ W,
                                                   const float* __restrict__ b_ih) {
    __shared__ float As_[16][68];
    __shared__ float Ws_[16][196];
    __shared__ float bihs[192];
    const float* __restrict__ h_in = g_h[0];
    const int tid = threadIdx.x;
    const int tx = tid & 15, ty = tid >> 4;
    const int m0 = blockIdx.x * 64, j0 = blockIdx.y * 64;
    if (tid < 192) bihs[tid] = b_ih[(tid >> 6) * HH + j0 + (tid & 63)];

    float acc[4][12];
#pragma unroll
    for (int i = 0; i < 4; i++)
#pragma unroll
        for (int j = 0; j < 12; j++) acc[i][j] = 0.0f;
    const int r = tid >> 2, kq = (tid & 3) << 2;
    for (int k0 = 0; k0 < HH; k0 += 16) {
        const float4 av  = *(const float4*)(h_in + (size_t)(m0 + r) * HH + k0 + kq);
        const float4 wv0 = *(const float4*)(W + (size_t)(j0 + r) * 528 + k0 + kq);
        const float4 wv1 = *(const float4*)(W + (size_t)(HH + j0 + r) * 528 + k0 + kq);
        const float4 wv2 = *(const float4*)(W + (size_t)(2 * HH + j0 + r) * 528 + k0 + kq);
        __syncthreads();
        As_[kq + 0][r] = av.x; As_[kq + 1][r] = av.y; As_[kq + 2][r] = av.z; As_[kq + 3][r] = av.w;
        Ws_[kq + 0][r] = wv0.x; Ws_[kq + 1][r] = wv0.y; Ws_[kq + 2][r] = wv0.z; Ws_[kq + 3][r] = wv0.w;
        Ws_[kq + 0][64 + r] = wv1.x; Ws_[kq + 1][64 + r] = wv1.y; Ws_[kq + 2][64 + r] = wv1.z; Ws_[kq + 3][64 + r] = wv1.w;
        Ws_[kq + 0][128 + r] = wv2.x; Ws_[kq + 1][128 + r] = wv2.y; Ws_[kq + 2][128 + r] = wv2.z; Ws_[kq + 3][128 + r] = wv2.w;
        __syncthreads();
#pragma unroll
        for (int kk = 0; kk < 16; kk++) {
            const float4 a = *(const float4*)&As_[kk][ty << 2];
            const float4 b0 = *(const float4*)&Ws_[kk][tx << 2];
            const float4 b1 = *(const float4*)&Ws_[kk][64 + (tx << 2)];
            const float4 b2 = *(const float4*)&Ws_[kk][128 + (tx << 2)];
            const float am[4] = {a.x, a.y, a.z, a.w};
            const float bn[12] = {b0.x, b0.y, b0.z, b0.w, b1.x, b1.y, b1.z, b1.w,
                                  b2.x, b2.y, b2.z, b2.w};
#pragma unroll
            for (int i = 0; i < 4; i++)
#pragma unroll
                for (int j = 0; j < 12; j++) acc[i][j] += am[i] * bn[j];
        }
    }
    const int c = tx << 2;
#pragma unroll
    for (int i = 0; i < 4; i++) {
        const int row = m0 + (ty << 2) + i;
#pragma unroll
        for (int g = 0; g < 3; g++) {
            float4 o;
            o.x = acc[i][g * 4 + 0] + bihs[g * 64 + c + 0];
            o.y = acc[i][g * 4 + 1] + bihs[g * 64 + c + 1];
            o.z = acc[i][g * 4 + 2] + bihs[g * 64 + c + 2];
            o.w = acc[i][g * 4 + 3] + bihs[g * 64 + c + 3];
            *(float4*)&g_gibase[(size_t)row * GG + g * HH + j0 + c] = o;
        }
    }
}

extern "C" void kernel_launch(void* const* d_in, const int* in_sizes, int n_in,
                              void* d_out, int out_size) {
    const float* lag      = (const float*)d_in[0];
    const float* curr     = (const float*)d_in[1];
    const float* W_ih_enc = (const float*)d_in[2];
    const float* W_hh_enc = (const float*)d_in[3];
    const float* b_ih_enc = (const float*)d_in[4];
    const float* b_hh_enc = (const float*)d_in[5];
    const float* W_ih_dec = (const float*)d_in[6];
    const float* W_hh_dec = (const float*)d_in[7];
    const float* b_ih_dec = (const float*)d_in[8];
    const float* b_hh_dec = (const float*)d_in[9];
    const float* W_dense  = (const float*)d_in[10];
    const float* b_dense  = (const float*)d_in[11];
    float* out = (float*)d_out;

    cudaFuncSetAttribute(rnn_persist<0, 8, TENC>,
                         cudaFuncAttributeMaxDynamicSharedMemorySize, SMEM_P);
    cudaFuncSetAttribute(rnn_persist<1, 16, TDEC>,
                         cudaFuncAttributeMaxDynamicSharedMemorySize, SMEM_P);

    prep_Bq_kernel<<<384, 256>>>(W_hh_enc, W_hh_dec);
    prep_bc_kernel<<<2, 256>>>(b_ih_enc, b_hh_enc, b_ih_dec, b_hh_dec);
    zero_h_kernel<<<256, 256>>>(0);

    const dim3 grid(16, 8);
    rnn_persist<0, 8, TENC><<<grid, NT, SMEM_P>>>(lag, W_ih_enc,
                                                  (const float*)0, (const float*)0,
                                                  (float*)0);
    // 168 even -> h_T in g_h[0]
    base_kernel<<<grid, 256>>>(W_ih_dec, b_ih_dec);
    zero_h_kernel<<<256, 256>>>(1);
    rnn_persist<1, 16, TDEC><<<grid, NT, SMEM_P>>>(curr, W_ih_dec,
                                                   W_dense, b_dense, out);
}

// round 14
// speedup vs baseline: 1.6445x; 1.0824x over previous
#include <cuda_runtime.h>
#include <math.h>
#include <stdint.h>

#define BB   1024
#define HH   512
#define GG   1536
#define TENC 168
#define TDEC 24
#define NCH  16
#define NCTA 128
#define NT   512
// persistent-kernel smem layout: B resident + Wxs + fBs + quant staging
#define BSM_BYTES (16 * 12288)               // 196608
#define WXS_OFF  BSM_BYTES
#define FBS_OFF  (WXS_OFF + 192 * 16 * 4)
#define SQ_OFF   (FBS_OFF + 192 * 4)         // 209664, 16B aligned
#define SMEM_P   (SQ_OFF + 8192 + 64)        // ~218 KB

// ---------------- persistent device state ----------------
__device__ float g_h[2][BB * HH];            // fp32 h (buffer 0 used)
// int8 state in mma-A-FRAGMENT layout: [(m/16)][chunk][lane] -> 16B = {a0,a1,a2,a3}
__device__ __align__(16) signed char g_hqf[2][2][BB * HH];   // [buf][hi/lo]
__device__ float g_gibase[BB * GG];
__device__ __align__(16) signed char g_Bq[2][2][GG * HH];    // [enc/dec][hi/lo]
__device__ float g_fB[2][GG];
__device__ float g_bc[2][4 * HH];
__device__ volatile unsigned g_flags[NCTA];  // per-CTA barrier counters (monotonic)
__device__ volatile unsigned g_gen2;

__device__ __forceinline__ float sigmoidf_(float x) { return 1.0f / (1.0f + expf(-x)); }

__device__ __forceinline__ void ldm4(uint32_t r[4], uint32_t a) {
    asm volatile("ldmatrix.sync.aligned.m8n8.x4.shared.b16 {%0,%1,%2,%3}, [%4];"
                 : "=r"(r[0]), "=r"(r[1]), "=r"(r[2]), "=r"(r[3]) : "r"(a));
}
__device__ __forceinline__ void mmai(int* d, const uint32_t* a, uint32_t b0, uint32_t b1) {
    asm volatile(
        "mma.sync.aligned.m16n8k32.row.col.s32.s8.s8.s32 "
        "{%0,%1,%2,%3},{%4,%5,%6,%7},{%8,%9},{%0,%1,%2,%3};"
        : "+r"(d[0]), "+r"(d[1]), "+r"(d[2]), "+r"(d[3])
        : "r"(a[0]), "r"(a[1]), "r"(a[2]), "r"(a[3]), "r"(b0), "r"(b1));
}
__device__ __forceinline__ void cpa16(uint32_t dst, const void* src) {
    asm volatile("cp.async.cg.shared.global [%0], [%1], 16;" :: "r"(dst), "l"(src));
}
__device__ __forceinline__ uint4 ldcg128(const signed char* p) {
    uint4 v;
    asm volatile("ld.global.cg.v4.b32 {%0,%1,%2,%3}, [%4];"
                 : "=r"(v.x), "=r"(v.y), "=r"(v.z), "=r"(v.w) : "l"(p));
    return v;
}
__device__ __forceinline__ float ldcgf(const float* p) {
    float v; asm volatile("ld.global.cg.f32 %0, [%1];" : "=f"(v) : "l"(p)); return v;
}

// flag-array grid barrier; target is the per-thread monotonic barrier count.
__device__ __forceinline__ void gsync(unsigned& target, int cta) {
    const int tid = threadIdx.x;
    __syncthreads();
    if (tid == 0) {
        __threadfence();
        g_flags[cta] = target;
    }
    if (cta == 0 && (tid >> 5) == 0) {
        const int l = tid & 31;
        for (;;) {
            unsigned mn = 0xffffffffu;
#pragma unroll
            for (int i = 0; i < 4; i++) {
                unsigned f = g_flags[l + i * 32];
                mn = (f < mn) ? f : mn;
            }
            if (__all_sync(0xffffffffu, mn >= target)) break;
            __nanosleep(32);
        }
        if (l == 0) { __threadfence(); g_gen2 = target; }
    } else if (tid == 0) {
        while (g_gen2 < target) __nanosleep(32);
        __threadfence();
    }
    __syncthreads();
    target++;
}

// ---------------- prep kernels ----------------
__global__ void prep_Bq_kernel(const float* __restrict__ Whe, const float* __restrict__ Whd) {
    const int gw = blockIdx.x * (blockDim.x >> 5) + (threadIdx.x >> 5);
    if (gw >= 2 * GG) return;
    const int which = gw / GG, G = gw - which * GG;
    const int lane = threadIdx.x & 31;
    const float* __restrict__ W = which ? Whd : Whe;
    const size_t base = (size_t)G * HH;
    float mx = 0.0f;
    for (int k = lane; k < HH; k += 32) mx = fmaxf(mx, fabsf(W[base + k]));
#pragma unroll
    for (int off = 16; off; off >>= 1) mx = fmaxf(mx, __shfl_xor_sync(0xffffffffu, mx, off));
    const float s1 = (mx > 0.0f) ? 127.0f / mx : 1.0f;
    const float inv1 = 1.0f / s1;
    for (int k = lane; k < HH; k += 32) {
        const float w = W[base + k];
        const int hi = __float2int_rn(w * s1);
        const int lo = __float2int_rn((w - (float)hi * inv1) * (s1 * 254.0f));
        g_Bq[which][0][base + k] = (signed char)hi;
        g_Bq[which][1][base + k] = (signed char)lo;
    }
    if (lane == 0) g_fB[which][G] = inv1 * (1.0f / 127.0f);
}
__global__ void prep_bc_kernel(const float* __restrict__ bie, const float* __restrict__ bhe,
                               const float* __restrict__ bid, const float* __restrict__ bhd) {
    for (int c = blockIdx.x * blockDim.x + threadIdx.x; c < HH; c += gridDim.x * blockDim.x) {
        g_bc[0][c]          = bie[c] + bhe[c];
        g_bc[0][HH + c]     = bie[512 + c] + bhe[512 + c];
        g_bc[0][2 * HH + c] = bie[1024 + c];
        g_bc[0][3 * HH + c] = bhe[1024 + c];
        g_bc[1][c]          = bhd[c];
        g_bc[1][HH + c]     = bhd[512 + c];
        g_bc[1][2 * HH + c] = 0.0f;
        g_bc[1][3 * HH + c] = bhd[1024 + c];
    }
}
__global__ void zero_q_kernel(int buf) {
    for (int i = blockIdx.x * blockDim.x + threadIdx.x; i < BB * HH;
         i += gridDim.x * blockDim.x) {
        g_hqf[buf][0][i] = 0;
        g_hqf[buf][1][i] = 0;
    }
}

// ---------------- persistent RNN kernel ----------------
// 128 CTAs = 16 m-tiles x 8 j-tiles; 512 threads = 4 m-warps x 4 n-warps.
// B resident in smem; A (int8 state) in fragment layout; h carried in registers.
template <int DEC, int E, int T>
__global__ __launch_bounds__(NT) void rnn_persist(
    const float* __restrict__ xall, const float* __restrict__ Wxg,
    const float* __restrict__ Wd, const float* __restrict__ bd,
    float* __restrict__ out) {
    extern __shared__ char dsm[];
    __shared__ unsigned s_tgt;
    const int tid = threadIdx.x, w = tid >> 5, l = tid & 31;
    const int cta = blockIdx.y * 16 + blockIdx.x;
    const int m0 = blockIdx.x * 64, j0 = blockIdx.y * 64;
    const uint32_t sB = (uint32_t)__cvta_generic_to_shared(dsm);
    float* Wxs = (float*)(dsm + WXS_OFF);
    float* fBs = (float*)(dsm + FBS_OFF);
    char* sQ  = dsm + SQ_OFF;

    // one-time prologue: barrier count, fBs, Wxs, B->smem
    if (tid == 0) s_tgt = g_flags[cta] + 1;
    if (tid < 192) fBs[tid] = g_fB[DEC][(tid >> 6) * HH + j0 + (tid & 63)];
    for (int idx = tid; idx < 192 * E; idx += NT) {
        const int n = idx / E, e = idx - n * E;
        const int G = (n >> 6) * HH + j0 + (n & 63);
        Wxs[idx] = DEC ? Wxg[(size_t)G * 528 + 512 + e] : Wxg[G * 8 + e];
    }
    {
        const signed char* Bh = g_Bq[DEC][0];
        const signed char* Bl = g_Bq[DEC][1];
        for (int i = tid; i < 12288; i += NT) {
            const int ch = i / 768, rem = i - ch * 768;
            const int sp = rem / 384, rem2 = rem - sp * 384;
            const int row = rem2 >> 1, kh = rem2 & 1;
            const int G = (row >> 6) * HH + j0 + (row & 63);
            cpa16(sB + ch * 12288 + sp * 6144 + kh * 3072 + row * 16,
                  (sp ? Bl : Bh) + (size_t)G * HH + ch * 32 + kh * 16);
        }
        asm volatile("cp.async.commit_group;");
        asm volatile("cp.async.wait_group 0;");
    }
    __syncthreads();
    unsigned target = s_tgt;

    const int mbase = (w >> 2) * 16, nloc = (w & 3) * 16;
    const int mblk = w >> 2;                 // local m-16-block 0..3
    const int brow = (l & 7) + ((l >> 4) & 1) * 8, bhalf = (l >> 3) & 1;
    const int ablk = (m0 >> 4) + mblk;       // global m-16-block
    const int jc0 = j0 >> 5;                 // this CTA's first chunk index
    const float* __restrict__ bc = g_bc[DEC];
    const float bd0 = DEC ? bd[0] : 0.0f;
    const int qr = l >> 2, qc = (l & 3) * 2;
    const float INV254 = 1.0f / 254.0f;

    float hreg[2][2][2];                     // [nj][hf][cc], init h0 = 0
#pragma unroll
    for (int a = 0; a < 2; a++)
#pragma unroll
        for (int b = 0; b < 2; b++)
#pragma unroll
            for (int c = 0; c < 2; c++) hreg[a][b][c] = 0.0f;

    for (int t = 0; t < T; t++) {
        const int pi = t & 1, po = pi ^ 1;

        const signed char* pAh = g_hqf[pi][0] + (size_t)ablk * 8192 + l * 16;
        const signed char* pAl = g_hqf[pi][1] + (size_t)ablk * 8192 + l * 16;

        int P1[3][2][4], P2[3][2][4];
#pragma unroll
        for (int g = 0; g < 3; g++)
#pragma unroll
            for (int b = 0; b < 2; b++)
#pragma unroll
                for (int q = 0; q < 4; q++) { P1[g][b][q] = 0; P2[g][b][q] = 0; }

        uint4 Ah[2], Al[2];
        Ah[0] = ldcg128(pAh);        Al[0] = ldcg128(pAl);
        Ah[1] = ldcg128(pAh + 512);  Al[1] = ldcg128(pAl + 512);

#pragma unroll
        for (int ch = 0; ch < NCH; ch++) {
            uint4 nh, nl;
            if (ch + 2 < NCH) { nh = ldcg128(pAh + (ch + 2) * 512);
                                nl = ldcg128(pAl + (ch + 2) * 512); }
            const uint32_t* ah = (const uint32_t*)&Ah[ch & 1];
            const uint32_t* al = (const uint32_t*)&Al[ch & 1];
#pragma unroll
            for (int g = 0; g < 3; g++) {
                const uint32_t rbase = sB + ch * 12288 + bhalf * 3072 + (g * 64 + nloc + brow) * 16;
                uint32_t bf[4];
                ldm4(bf, rbase);                       // B hi
                mmai(P1[g][0], ah, bf[0], bf[1]);
                mmai(P1[g][1], ah, bf[2], bf[3]);
                mmai(P2[g][0], al, bf[0], bf[1]);
                mmai(P2[g][1], al, bf[2], bf[3]);
                ldm4(bf, rbase + 6144);                // B lo
                mmai(P2[g][0], ah, bf[0], bf[1]);
                mmai(P2[g][1], ah, bf[2], bf[3]);
            }
            if (ch + 2 < NCH) { Ah[ch & 1] = nh; Al[ch & 1] = nl; }
        }

        // ---- fused GRU epilogue (h in registers; quant staged to smem) ----
        signed char* __restrict__ hf_hi = g_hqf[po][0];
        signed char* __restrict__ hf_lo = g_hqf[po][1];
        const float* __restrict__ xg = xall + (size_t)t * BB * E;
        const bool store_h = DEC || (t == T - 1);

#pragma unroll
        for (int hf = 0; hf < 2; hf++) {
            const int row16 = qr + hf * 8;
            const int m = m0 + mbase + row16;
            float xv[E];
#pragma unroll
            for (int e = 0; e < E; e++) xv[e] = __ldg(xg + m * E + e);
#pragma unroll
            for (int nj = 0; nj < 2; nj++) {
                const int cl0 = nloc + nj * 8 + qc;
                const int cb = j0 + cl0;
                float2 gr = {0.f, 0.f}, gz = {0.f, 0.f}, gn = {0.f, 0.f};
                if (DEC) {
                    gr = *(const float2*)&g_gibase[(size_t)m * GG + cb];
                    gz = *(const float2*)&g_gibase[(size_t)m * GG + HH + cb];
                    gn = *(const float2*)&g_gibase[(size_t)m * GG + 2 * HH + cb];
                }
                float hv[2]; int hqi[2], hql[2];
#pragma unroll
                for (int cc = 0; cc < 2; cc++) {
                    const int q = hf * 2 + cc, cl = cl0 + cc, c = cb + cc;
                    const float pr = ((float)P1[0][nj][q] + (float)P2[0][nj][q] * INV254) * fBs[cl];
                    const float pz = ((float)P1[1][nj][q] + (float)P2[1][nj][q] * INV254) * fBs[64 + cl];
                    const float pn = ((float)P1[2][nj][q] + (float)P2[2][nj][q] * INV254) * fBs[128 + cl];
                    float xr = 0.f, xz = 0.f, xn = 0.f;
#pragma unroll
                    for (int e = 0; e < E; e++) {
                        xr += xv[e] * Wxs[cl * E + e];
                        xz += xv[e] * Wxs[(64 + cl) * E + e];
                        xn += xv[e] * Wxs[(128 + cl) * E + e];
                    }
                    const float ir = (DEC ? (cc ? gr.y : gr.x) : 0.f) + xr;
                    const float iz = (DEC ? (cc ? gz.y : gz.x) : 0.f) + xz;
                    const float in0 = (DEC ? (cc ? gn.y : gn.x) : 0.f) + xn;
                    const float rr = sigmoidf_(pr + ir + bc[c]);
                    const float zz = sigmoidf_(pz + iz + bc[HH + c]);
                    const float nn = tanhf(in0 + bc[2 * HH + c] + rr * (pn + bc[3 * HH + c]));
                    const float h = (1.0f - zz) * nn + zz * hreg[nj][hf][cc];
                    hreg[nj][hf][cc] = h;
                    hv[cc] = h;
                    const int hi = __float2int_rn(h * 127.0f);
                    hqi[cc] = hi;
                    hql[cc] = __float2int_rn((h - (float)hi * (1.0f / 127.0f)) * 32258.0f);
                }
                if (store_h) {
                    float2 ho; ho.x = hv[0]; ho.y = hv[1];
                    *(float2*)&g_h[0][(size_t)m * HH + cb] = ho;
                }
                // stage quant bytes (same bytes as direct fragment store)
                const int lc = (cb >> 5) - jc0;            // 0..1
                const int kin = cb & 31;
                const int kh = kin >> 4, kq = kin & 15;
                const int lp = ((row16 & 7) << 2) + (kq >> 2);
                const int rg = kh * 2 + (row16 >> 3);
                const int so = mblk * 1024 + lc * 512 + lp * 16 + rg * 4 + (kq & 3);
                *(char2*)(sQ + so)        = make_char2((char)hqi[0], (char)hqi[1]);
                *(char2*)(sQ + 4096 + so) = make_char2((char)hql[0], (char)hql[1]);
            }
        }
        __syncthreads();
        // cooperative coalesced copy of staged quant records
        {
            const int sp = tid >> 8, rem = tid & 255;
            const int mb = rem >> 6, r2 = rem & 63;
            const int lc = r2 >> 5, lp = r2 & 31;
            const uint4 v = *(const uint4*)(sQ + sp * 4096 + mb * 1024 + lc * 512 + lp * 16);
            signed char* dst = (sp ? hf_lo : hf_hi) +
                               (size_t)((m0 >> 4) + mb) * 8192 + (jc0 + lc) * 512 + lp * 16;
            *(uint4*)dst = v;
        }

        gsync(target, cta);   // h^t quant state visible everywhere

        if (DEC && blockIdx.y == 0) {   // fused dense head for step t
            const float* __restrict__ hb = g_h[0];
#pragma unroll
            for (int r = 0; r < 4; r++) {
                const int row = m0 + (w << 2) + r;
                float s = 0.0f;
                for (int k = l; k < HH; k += 32)
                    s += ldcgf(hb + (size_t)row * HH + k) * Wd[k];
#pragma unroll
                for (int off = 16; off; off >>= 1) s += __shfl_down_sync(0xffffffffu, s, off);
                if (l == 0) out[row * TDEC + t] = s + bd0;
            }
        }
    }
}

// ---------------- fp32 base GEMM (once, between phases) ----------------
__global__ __launch_bounds__(256) void base_kernel(const float* __restrict__ W,
                                                   const float* __restrict__ b_ih) {
    __shared__ float As_[16][68];
    __shared__ float Ws_[16][196];
    __shared__ float bihs[192];
    const float* __restrict__ h_in = g_h[0];
    const int tid = threadIdx.x;
    const int tx = tid & 15, ty = tid >> 4;
    const int m0 = blockIdx.x * 64, j0 = blockIdx.y * 64;
    if (tid < 192) bihs[tid] = b_ih[(tid >> 6) * HH + j0 + (tid & 63)];

    float acc[4][12];
#pragma unroll
    for (int i = 0; i < 4; i++)
#pragma unroll
        for (int j = 0; j < 12; j++) acc[i][j] = 0.0f;
    const int r = tid >> 2, kq = (tid & 3) << 2;
    for (int k0 = 0; k0 < HH; k0 += 16) {
        const float4 av  = *(const float4*)(h_in + (size_t)(m0 + r) * HH + k0 + kq);
        const float4 wv0 = *(const float4*)(W + (size_t)(j0 + r) * 528 + k0 + kq);
        const float4 wv1 = *(const float4*)(W + (size_t)(HH + j0 + r) * 528 + k0 + kq);
        const float4 wv2 = *(const float4*)(W + (size_t)(2 * HH + j0 + r) * 528 + k0 + kq);
        __syncthreads();
        As_[kq + 0][r] = av.x; As_[kq + 1][r] = av.y; As_[kq + 2][r] = av.z; As_[kq + 3][r] = av.w;
        Ws_[kq + 0][r] = wv0.x; Ws_[kq + 1][r] = wv0.y; Ws_[kq + 2][r] = wv0.z; Ws_[kq + 3][r] = wv0.w;
        Ws_[kq + 0][64 + r] = wv1.x; Ws_[kq + 1][64 + r] = wv1.y; Ws_[kq + 2][64 + r] = wv1.z; Ws_[kq + 3][64 + r] = wv1.w;
        Ws_[kq + 0][128 + r] = wv2.x; Ws_[kq + 1][128 + r] = wv2.y; Ws_[kq + 2][128 + r] = wv2.z; Ws_[kq + 3][128 + r] = wv2.w;
        __syncthreads();
#pragma unroll
        for (int kk = 0; kk < 16; kk++) {
            const float4 a = *(const float4*)&As_[kk][ty << 2];
            const float4 b0 = *(const float4*)&Ws_[kk][tx << 2];
            const float4 b1 = *(const float4*)&Ws_[kk][64 + (tx << 2)];
            const float4 b2 = *(const float4*)&Ws_[kk][128 + (tx << 2)];
            const float am[4] = {a.x, a.y, a.z, a.w};
            const float bn[12] = {b0.x, b0.y, b0.z, b0.w, b1.x, b1.y, b1.z, b1.w,
                                  b2.x, b2.y, b2.z, b2.w};
#pragma unroll
            for (int i = 0; i < 4; i++)
#pragma unroll
                for (int j = 0; j < 12; j++) acc[i][j] += am[i] * bn[j];
        }
    }
    const int c = tx << 2;
#pragma unroll
    for (int i = 0; i < 4; i++) {
        const int row = m0 + (ty << 2) + i;
#pragma unroll
        for (int g = 0; g < 3; g++) {
            float4 o;
            o.x = acc[i][g * 4 + 0] + bihs[g * 64 + c + 0];
            o.y = acc[i][g * 4 + 1] + bihs[g * 64 + c + 1];
            o.z = acc[i][g * 4 + 2] + bihs[g * 64 + c + 2];
            o.w = acc[i][g * 4 + 3] + bihs[g * 64 + c + 3];
            *(float4*)&g_gibase[(size_t)row * GG + g * HH + j0 + c] = o;
        }
    }
}

extern "C" void kernel_launch(void* const* d_in, const int* in_sizes, int n_in,
                              void* d_out, int out_size) {
    const float* lag      = (const float*)d_in[0];
    const float* curr     = (const float*)d_in[1];
    const float* W_ih_enc = (const float*)d_in[2];
    const float* W_hh_enc = (const float*)d_in[3];
    const float* b_ih_enc = (const float*)d_in[4];
    const float* b_hh_enc = (const float*)d_in[5];
    const float* W_ih_dec = (const float*)d_in[6];
    const float* W_hh_dec = (const float*)d_in[7];
    const float* b_ih_dec = (const float*)d_in[8];
    const float* b_hh_dec = (const float*)d_in[9];
    const float* W_dense  = (const float*)d_in[10];
    const float* b_dense  = (const float*)d_in[11];
    float* out = (float*)d_out;

    cudaFuncSetAttribute(rnn_persist<0, 8, TENC>,
                         cudaFuncAttributeMaxDynamicSharedMemorySize, SMEM_P);
    cudaFuncSetAttribute(rnn_persist<1, 16, TDEC>,
                         cudaFuncAttributeMaxDynamicSharedMemorySize, SMEM_P);

    prep_Bq_kernel<<<384, 256>>>(W_hh_enc, W_hh_dec);
    prep_bc_kernel<<<2, 256>>>(b_ih_enc, b_hh_enc, b_ih_dec, b_hh_dec);
    zero_q_kernel<<<256, 256>>>(0);

    const dim3 grid(16, 8);
    rnn_persist<0, 8, TENC><<<grid, NT, SMEM_P>>>(lag, W_ih_enc,
                                                  (const float*)0, (const float*)0,
                                                  (float*)0);
    base_kernel<<<grid, 256>>>(W_ih_dec, b_ih_dec);
    zero_q_kernel<<<256, 256>>>(0);
    rnn_persist<1, 16, TDEC><<<grid, NT, SMEM_P>>>(curr, W_ih_dec,
                                                   W_dense, b_dense, out);
}

// round 15
// speedup vs baseline: 1.6768x; 1.0196x over previous
#include <cuda_runtime.h>
#include <math.h>
#include <stdint.h>

#define BB   1024
#define HH   512
#define GG   1536
#define TENC 168
#define TDEC 24
#define NCH  16
#define NCTA 128
#define NT   512
// persistent-kernel smem layout: B resident + Wxs + fBs + quant staging
#define BSM_BYTES (16 * 12288)               // 196608
#define WXS_OFF  BSM_BYTES
#define FBS_OFF  (WXS_OFF + 192 * 16 * 4)
#define SQ_OFF   (FBS_OFF + 192 * 4)         // 16B aligned
#define SMEM_P   (SQ_OFF + 8192 + 64)        // ~218 KB

// ---------------- persistent device state ----------------
__device__ float g_h[2][BB * HH];            // fp32 h (buffer 0 used)
// int8 state in mma-A-FRAGMENT layout: [(m/16)][chunk][lane] -> 16B = {a0,a1,a2,a3}
__device__ __align__(16) signed char g_hqf[2][2][BB * HH];   // [buf][hi/lo]
__device__ float g_gibase[BB * GG];
__device__ __align__(16) signed char g_Bq[2][2][GG * HH];    // [enc/dec][hi/lo]
__device__ float g_fB[2][GG];
__device__ float g_bc[2][4 * HH];
__device__ volatile unsigned g_flags[NCTA];  // per-CTA barrier counters (monotonic)

__device__ __forceinline__ float sigmoidf_(float x) { return 1.0f / (1.0f + expf(-x)); }

__device__ __forceinline__ void ldm4(uint32_t r[4], uint32_t a) {
    asm volatile("ldmatrix.sync.aligned.m8n8.x4.shared.b16 {%0,%1,%2,%3}, [%4];"
                 : "=r"(r[0]), "=r"(r[1]), "=r"(r[2]), "=r"(r[3]) : "r"(a));
}
__device__ __forceinline__ void mmai(int* d, const uint32_t* a, uint32_t b0, uint32_t b1) {
    asm volatile(
        "mma.sync.aligned.m16n8k32.row.col.s32.s8.s8.s32 "
        "{%0,%1,%2,%3},{%4,%5,%6,%7},{%8,%9},{%0,%1,%2,%3};"
        : "+r"(d[0]), "+r"(d[1]), "+r"(d[2]), "+r"(d[3])
        : "r"(a[0]), "r"(a[1]), "r"(a[2]), "r"(a[3]), "r"(b0), "r"(b1));
}
__device__ __forceinline__ void cpa16(uint32_t dst, const void* src) {
    asm volatile("cp.async.cg.shared.global [%0], [%1], 16;" :: "r"(dst), "l"(src));
}
__device__ __forceinline__ uint4 ldcg128(const signed char* p) {
    uint4 v;
    asm volatile("ld.global.cg.v4.b32 {%0,%1,%2,%3}, [%4];"
                 : "=r"(v.x), "=r"(v.y), "=r"(v.z), "=r"(v.w) : "l"(p));
    return v;
}
__device__ __forceinline__ float ldcgf(const float* p) {
    float v; asm volatile("ld.global.cg.f32 %0, [%1];" : "=f"(v) : "l"(p)); return v;
}

// 8-CTA sub-barrier over the bx-group (CTAs sharing blockIdx.x).
// Single hop: post own flag, 8 threads poll the group's flags directly.
__device__ __forceinline__ void gsync8(unsigned& target, int cta, int bx) {
    const int tid = threadIdx.x;
    __syncthreads();
    if (tid == 0) { __threadfence(); g_flags[cta] = target; }
    if (tid < 8) {
        const int fi = tid * 16 + bx;       // cta index of group member 'tid'
        while (g_flags[fi] < target) __nanosleep(32);
        __threadfence();                     // acquire
    }
    __syncthreads();
    target++;
}

// ---------------- prep kernels ----------------
__global__ void prep_Bq_kernel(const float* __restrict__ Whe, const float* __restrict__ Whd) {
    const int gw = blockIdx.x * (blockDim.x >> 5) + (threadIdx.x >> 5);
    if (gw >= 2 * GG) return;
    const int which = gw / GG, G = gw - which * GG;
    const int lane = threadIdx.x & 31;
    const float* __restrict__ W = which ? Whd : Whe;
    const size_t base = (size_t)G * HH;
    float mx = 0.0f;
    for (int k = lane; k < HH; k += 32) mx = fmaxf(mx, fabsf(W[base + k]));
#pragma unroll
    for (int off = 16; off; off >>= 1) mx = fmaxf(mx, __shfl_xor_sync(0xffffffffu, mx, off));
    const float s1 = (mx > 0.0f) ? 127.0f / mx : 1.0f;
    const float inv1 = 1.0f / s1;
    for (int k = lane; k < HH; k += 32) {
        const float w = W[base + k];
        const int hi = __float2int_rn(w * s1);
        const int lo = __float2int_rn((w - (float)hi * inv1) * (s1 * 254.0f));
        g_Bq[which][0][base + k] = (signed char)hi;
        g_Bq[which][1][base + k] = (signed char)lo;
    }
    if (lane == 0) g_fB[which][G] = inv1 * (1.0f / 127.0f);
}
__global__ void prep_bc_kernel(const float* __restrict__ bie, const float* __restrict__ bhe,
                               const float* __restrict__ bid, const float* __restrict__ bhd) {
    for (int c = blockIdx.x * blockDim.x + threadIdx.x; c < HH; c += gridDim.x * blockDim.x) {
        g_bc[0][c]          = bie[c] + bhe[c];
        g_bc[0][HH + c]     = bie[512 + c] + bhe[512 + c];
        g_bc[0][2 * HH + c] = bie[1024 + c];
        g_bc[0][3 * HH + c] = bhe[1024 + c];
        g_bc[1][c]          = bhd[c];
        g_bc[1][HH + c]     = bhd[512 + c];
        g_bc[1][2 * HH + c] = 0.0f;
        g_bc[1][3 * HH + c] = bhd[1024 + c];
    }
}
__global__ void zero_q_kernel(int buf) {
    for (int i = blockIdx.x * blockDim.x + threadIdx.x; i < BB * HH;
         i += gridDim.x * blockDim.x) {
        g_hqf[buf][0][i] = 0;
        g_hqf[buf][1][i] = 0;
    }
}

// ---------------- persistent RNN kernel ----------------
// 128 CTAs = 16 m-tiles x 8 j-tiles; 512 threads = 4 m-warps x 4 n-warps.
// B resident in smem; A (int8 state) in fragment layout; h carried in registers.
// Cross-step sync scoped to the 8-CTA bx-group (sole data dependence).
template <int DEC, int E, int T>
__global__ __launch_bounds__(NT) void rnn_persist(
    const float* __restrict__ xall, const float* __restrict__ Wxg,
    const float* __restrict__ Wd, const float* __restrict__ bd,
    float* __restrict__ out) {
    extern __shared__ char dsm[];
    __shared__ unsigned s_tgt;
    const int tid = threadIdx.x, w = tid >> 5, l = tid & 31;
    const int cta = blockIdx.y * 16 + blockIdx.x;
    const int m0 = blockIdx.x * 64, j0 = blockIdx.y * 64;
    const uint32_t sB = (uint32_t)__cvta_generic_to_shared(dsm);
    float* Wxs = (float*)(dsm + WXS_OFF);
    float* fBs = (float*)(dsm + FBS_OFF);
    char* sQ  = dsm + SQ_OFF;

    // one-time prologue: barrier count, fBs, Wxs, B->smem
    if (tid == 0) s_tgt = g_flags[cta] + 1;
    if (tid < 192) fBs[tid] = g_fB[DEC][(tid >> 6) * HH + j0 + (tid & 63)];
    for (int idx = tid; idx < 192 * E; idx += NT) {
        const int n = idx / E, e = idx - n * E;
        const int G = (n >> 6) * HH + j0 + (n & 63);
        Wxs[idx] = DEC ? Wxg[(size_t)G * 528 + 512 + e] : Wxg[G * 8 + e];
    }
    {
        const signed char* Bh = g_Bq[DEC][0];
        const signed char* Bl = g_Bq[DEC][1];
        for (int i = tid; i < 12288; i += NT) {
            const int ch = i / 768, rem = i - ch * 768;
            const int sp = rem / 384, rem2 = rem - sp * 384;
            const int row = rem2 >> 1, kh = rem2 & 1;
            const int G = (row >> 6) * HH + j0 + (row & 63);
            cpa16(sB + ch * 12288 + sp * 6144 + kh * 3072 + row * 16,
                  (sp ? Bl : Bh) + (size_t)G * HH + ch * 32 + kh * 16);
        }
        asm volatile("cp.async.commit_group;");
        asm volatile("cp.async.wait_group 0;");
    }
    __syncthreads();
    unsigned target = s_tgt;

    const int mbase = (w >> 2) * 16, nloc = (w & 3) * 16;
    const int mblk = w >> 2;                 // local m-16-block 0..3
    const int brow = (l & 7) + ((l >> 4) & 1) * 8, bhalf = (l >> 3) & 1;
    const int ablk = (m0 >> 4) + mblk;       // global m-16-block
    const int jc0 = j0 >> 5;                 // this CTA's first chunk index
    const float* __restrict__ bc = g_bc[DEC];
    const float bd0 = DEC ? bd[0] : 0.0f;
    const int qr = l >> 2, qc = (l & 3) * 2;
    const float INV254 = 1.0f / 254.0f;

    float hreg[2][2][2];                     // [nj][hf][cc], init h0 = 0
#pragma unroll
    for (int a = 0; a < 2; a++)
#pragma unroll
        for (int b = 0; b < 2; b++)
#pragma unroll
            for (int c = 0; c < 2; c++) hreg[a][b][c] = 0.0f;

    for (int t = 0; t < T; t++) {
        const int pi = t & 1, po = pi ^ 1;

        const signed char* pAh = g_hqf[pi][0] + (size_t)ablk * 8192 + l * 16;
        const signed char* pAl = g_hqf[pi][1] + (size_t)ablk * 8192 + l * 16;

        int P1[3][2][4], P2[3][2][4];
#pragma unroll
        for (int g = 0; g < 3; g++)
#pragma unroll
            for (int b = 0; b < 2; b++)
#pragma unroll
                for (int q = 0; q < 4; q++) { P1[g][b][q] = 0; P2[g][b][q] = 0; }

        uint4 Ah[2], Al[2];
        Ah[0] = ldcg128(pAh);        Al[0] = ldcg128(pAl);
        Ah[1] = ldcg128(pAh + 512);  Al[1] = ldcg128(pAl + 512);

#pragma unroll
        for (int ch = 0; ch < NCH; ch++) {
            uint4 nh, nl;
            if (ch + 2 < NCH) { nh = ldcg128(pAh + (ch + 2) * 512);
                                nl = ldcg128(pAl + (ch + 2) * 512); }
            const uint32_t* ah = (const uint32_t*)&Ah[ch & 1];
            const uint32_t* al = (const uint32_t*)&Al[ch & 1];
#pragma unroll
            for (int g = 0; g < 3; g++) {
                const uint32_t rbase = sB + ch * 12288 + bhalf * 3072 + (g * 64 + nloc + brow) * 16;
                uint32_t bf[4];
                ldm4(bf, rbase);                       // B hi
                mmai(P1[g][0], ah, bf[0], bf[1]);
                mmai(P1[g][1], ah, bf[2], bf[3]);
                mmai(P2[g][0], al, bf[0], bf[1]);
                mmai(P2[g][1], al, bf[2], bf[3]);
                ldm4(bf, rbase + 6144);                // B lo
                mmai(P2[g][0], ah, bf[0], bf[1]);
                mmai(P2[g][1], ah, bf[2], bf[3]);
            }
            if (ch + 2 < NCH) { Ah[ch & 1] = nh; Al[ch & 1] = nl; }
        }

        // ---- fused GRU epilogue (h in registers; quant staged to smem) ----
        signed char* __restrict__ hf_hi = g_hqf[po][0];
        signed char* __restrict__ hf_lo = g_hqf[po][1];
        const float* __restrict__ xg = xall + (size_t)t * BB * E;
        const bool store_h = DEC || (t == T - 1);

#pragma unroll
        for (int hf = 0; hf < 2; hf++) {
            const int row16 = qr + hf * 8;
            const int m = m0 + mbase + row16;
            float xv[E];
#pragma unroll
            for (int e = 0; e < E; e++) xv[e] = __ldg(xg + m * E + e);
#pragma unroll
            for (int nj = 0; nj < 2; nj++) {
                const int cl0 = nloc + nj * 8 + qc;
                const int cb = j0 + cl0;
                float2 gr = {0.f, 0.f}, gz = {0.f, 0.f}, gn = {0.f, 0.f};
                if (DEC) {
                    gr = *(const float2*)&g_gibase[(size_t)m * GG + cb];
                    gz = *(const float2*)&g_gibase[(size_t)m * GG + HH + cb];
                    gn = *(const float2*)&g_gibase[(size_t)m * GG + 2 * HH + cb];
                }
                float hv[2]; int hqi[2], hql[2];
#pragma unroll
                for (int cc = 0; cc < 2; cc++) {
                    const int q = hf * 2 + cc, cl = cl0 + cc, c = cb + cc;
                    const float pr = ((float)P1[0][nj][q] + (float)P2[0][nj][q] * INV254) * fBs[cl];
                    const float pz = ((float)P1[1][nj][q] + (float)P2[1][nj][q] * INV254) * fBs[64 + cl];
                    const float pn = ((float)P1[2][nj][q] + (float)P2[2][nj][q] * INV254) * fBs[128 + cl];
                    float xr = 0.f, xz = 0.f, xn = 0.f;
#pragma unroll
                    for (int e = 0; e < E; e++) {
                        xr += xv[e] * Wxs[cl * E + e];
                        xz += xv[e] * Wxs[(64 + cl) * E + e];
                        xn += xv[e] * Wxs[(128 + cl) * E + e];
                    }
                    const float ir = (DEC ? (cc ? gr.y : gr.x) : 0.f) + xr;
                    const float iz = (DEC ? (cc ? gz.y : gz.x) : 0.f) + xz;
                    const float in0 = (DEC ? (cc ? gn.y : gn.x) : 0.f) + xn;
                    const float rr = sigmoidf_(pr + ir + bc[c]);
                    const float zz = sigmoidf_(pz + iz + bc[HH + c]);
                    const float nn = tanhf(in0 + bc[2 * HH + c] + rr * (pn + bc[3 * HH + c]));
                    const float h = (1.0f - zz) * nn + zz * hreg[nj][hf][cc];
                    hreg[nj][hf][cc] = h;
                    hv[cc] = h;
                    const int hi = __float2int_rn(h * 127.0f);
                    hqi[cc] = hi;
                    hql[cc] = __float2int_rn((h - (float)hi * (1.0f / 127.0f)) * 32258.0f);
                }
                if (store_h) {
                    float2 ho; ho.x = hv[0]; ho.y = hv[1];
                    *(float2*)&g_h[0][(size_t)m * HH + cb] = ho;
                }
                // stage quant bytes (same bytes as direct fragment store)
                const int lc = (cb >> 5) - jc0;            // 0..1
                const int kin = cb & 31;
                const int kh = kin >> 4, kq = kin & 15;
                const int lp = ((row16 & 7) << 2) + (kq >> 2);
                const int rg = kh * 2 + (row16 >> 3);
                const int so = mblk * 1024 + lc * 512 + lp * 16 + rg * 4 + (kq & 3);
                *(char2*)(sQ + so)        = make_char2((char)hqi[0], (char)hqi[1]);
                *(char2*)(sQ + 4096 + so) = make_char2((char)hql[0], (char)hql[1]);
            }
        }
        __syncthreads();
        // cooperative coalesced copy of staged quant records
        {
            const int sp = tid >> 8, rem = tid & 255;
            const int mb = rem >> 6, r2 = rem & 63;
            const int lc = r2 >> 5, lp = r2 & 31;
            const uint4 v = *(const uint4*)(sQ + sp * 4096 + mb * 1024 + lc * 512 + lp * 16);
            signed char* dst = (sp ? hf_lo : hf_hi) +
                               (size_t)((m0 >> 4) + mb) * 8192 + (jc0 + lc) * 512 + lp * 16;
            *(uint4*)dst = v;
        }

        gsync8(target, cta, blockIdx.x);   // bx-group's h^t state visible

        if (DEC && blockIdx.y == 0) {   // fused dense head for step t
            const float* __restrict__ hb = g_h[0];
#pragma unroll
            for (int r = 0; r < 4; r++) {
                const int row = m0 + (w << 2) + r;
                float s = 0.0f;
                for (int k = l; k < HH; k += 32)
                    s += ldcgf(hb + (size_t)row * HH + k) * Wd[k];
#pragma unroll
                for (int off = 16; off; off >>= 1) s += __shfl_down_sync(0xffffffffu, s, off);
                if (l == 0) out[row * TDEC + t] = s + bd0;
            }
        }
    }
}

// ---------------- fp32 base GEMM (once, between phases) ----------------
__global__ __launch_bounds__(256) void base_kernel(const float* __restrict__ W,
                                                   const float* __restrict__ b_ih) {
    __shared__ float As_[16][68];
    __shared__ float Ws_[16][196];
    __shared__ float bihs[192];
    const float* __restrict__ h_in = g_h[0];
    const int tid = threadIdx.x;
    const int tx = tid & 15, ty = tid >> 4;
    const int m0 = blockIdx.x * 64, j0 = blockIdx.y * 64;
    if (tid < 192) bihs[tid] = b_ih[(tid >> 6) * HH + j0 + (tid & 63)];

    float acc[4][12];
#pragma unroll
    for (int i = 0; i < 4; i++)
#pragma unroll
        for (int j = 0; j < 12; j++) acc[i][j] = 0.0f;
    const int r = tid >> 2, kq = (tid & 3) << 2;
    for (int k0 = 0; k0 < HH; k0 += 16) {
        const float4 av  = *(const float4*)(h_in + (size_t)(m0 + r) * HH + k0 + kq);
        const float4 wv0 = *(const float4*)(W + (size_t)(j0 + r) * 528 + k0 + kq);
        const float4 wv1 = *(const float4*)(W + (size_t)(HH + j0 + r) * 528 + k0 + kq);
        const float4 wv2 = *(const float4*)(W + (size_t)(2 * HH + j0 + r) * 528 + k0 + kq);
        __syncthreads();
        As_[kq + 0][r] = av.x; As_[kq + 1][r] = av.y; As_[kq + 2][r] = av.z; As_[kq + 3][r] = av.w;
        Ws_[kq + 0][r] = wv0.x; Ws_[kq + 1][r] = wv0.y; Ws_[kq + 2][r] = wv0.z; Ws_[kq + 3][r] = wv0.w;
        Ws_[kq + 0][64 + r] = wv1.x; Ws_[kq + 1][64 + r] = wv1.y; Ws_[kq + 2][64 + r] = wv1.z; Ws_[kq + 3][64 + r] = wv1.w;
        Ws_[kq + 0][128 + r] = wv2.x; Ws_[kq + 1][128 + r] = wv2.y; Ws_[kq + 2][128 + r] = wv2.z; Ws_[kq + 3][128 + r] = wv2.w;
        __syncthreads();
#pragma unroll
        for (int kk = 0; kk < 16; kk++) {
            const float4 a = *(const float4*)&As_[kk][ty << 2];
            const float4 b0 = *(const float4*)&Ws_[kk][tx << 2];
            const float4 b1 = *(const float4*)&Ws_[kk][64 + (tx << 2)];
            const float4 b2 = *(const float4*)&Ws_[kk][128 + (tx << 2)];
            const float am[4] = {a.x, a.y, a.z, a.w};
            const float bn[12] = {b0.x, b0.y, b0.z, b0.w, b1.x, b1.y, b1.z, b1.w,
                                  b2.x, b2.y, b2.z, b2.w};
#pragma unroll
            for (int i = 0; i < 4; i++)
#pragma unroll
                for (int j = 0; j < 12; j++) acc[i][j] += am[i] * bn[j];
        }
    }
    const int c = tx << 2;
#pragma unroll
    for (int i = 0; i < 4; i++) {
        const int row = m0 + (ty << 2) + i;
#pragma unroll
        for (int g = 0; g < 3; g++) {
            float4 o;
            o.x = acc[i][g * 4 + 0] + bihs[g * 64 + c + 0];
            o.y = acc[i][g * 4 + 1] + bihs[g * 64 + c + 1];
            o.z = acc[i][g * 4 + 2] + bihs[g * 64 + c + 2];
            o.w = acc[i][g * 4 + 3] + bihs[g * 64 + c + 3];
            *(float4*)&g_gibase[(size_t)row * GG + g * HH + j0 + c] = o;
        }
    }
}

extern "C" void kernel_launch(void* const* d_in, const int* in_sizes, int n_in,
                              void* d_out, int out_size) {
    const float* lag      = (const float*)d_in[0];
    const float* curr     = (const float*)d_in[1];
    const float* W_ih_enc = (const float*)d_in[2];
    const float* W_hh_enc = (const float*)d_in[3];
    const float* b_ih_enc = (const float*)d_in[4];
    const float* b_hh_enc = (const float*)d_in[5];
    const float* W_ih_dec = (const float*)d_in[6];
    const float* W_hh_dec = (const float*)d_in[7];
    const float* b_ih_dec = (const float*)d_in[8];
    const float* b_hh_dec = (const float*)d_in[9];
    const float* W_dense  = (const float*)d_in[10];
    const float* b_dense  = (const float*)d_in[11];
    float* out = (float*)d_out;

    cudaFuncSetAttribute(rnn_persist<0, 8, TENC>,
                         cudaFuncAttributeMaxDynamicSharedMemorySize, SMEM_P);
    cudaFuncSetAttribute(rnn_persist<1, 16, TDEC>,
                         cudaFuncAttributeMaxDynamicSharedMemorySize, SMEM_P);

    prep_Bq_kernel<<<384, 256>>>(W_hh_enc, W_hh_dec);
    prep_bc_kernel<<<2, 256>>>(b_ih_enc, b_hh_enc, b_ih_dec, b_hh_dec);
    zero_q_kernel<<<256, 256>>>(0);

    const dim3 grid(16, 8);
    rnn_persist<0, 8, TENC><<<grid, NT, SMEM_P>>>(lag, W_ih_enc,
                                                  (const float*)0, (const float*)0,
                                                  (float*)0);
    base_kernel<<<grid, 256>>>(W_ih_dec, b_ih_dec);
    zero_q_kernel<<<256, 256>>>(0);
    rnn_persist<1, 16, TDEC><<<grid, NT, SMEM_P>>>(curr, W_ih_dec,
                                                   W_dense, b_dense, out);
}